// round 8
// baseline (speedup 1.0000x reference)
#include <cuda_runtime.h>
#include <cuda_bf16.h>
#include <cstdint>
#include <math.h>

// Problem constants: x_seen (v=2, h=4, B=2048, C1=1024), x_unseen (2,4,2048,2048)
#define VDIM 2
#define HDIM 4
#define BDIM 2048
#define NDIM 4096   // v*B
#define C1D  1024
#define C2D  2048
#define EPSV 1e-07f
#define LN_EPS (-16.118095651f)
#define INV_TEMP 20.0f
#define TAU 1e-8f
#define K1 96       // max kept entries per seen row  (C1=1024)
#define K2 128      // max kept entries per unseen row (C2=2048)

#define PTOT (HDIM * C2D * C1D)   // 8388608 cells

// ---------------------------------------------------------------------------
// Device globals (never passed as kernel args from host — GB300/ATS trap!)
__device__ float  g_P[PTOT];        // dense p_joint accum, 32MB
__device__ float  g_cs_seen[HDIM * C1D];
__device__ float  g_cs_unseen[HDIM * C2D];
__device__ float  g_logps[HDIM * C1D];
__device__ double g_acc[2];         // [0]=sum p(lnp-lps) incl. EPS baseline, [1]=sum pu ln pu
__device__ int    g_done;

// ---------------------------------------------------------------------------
// 1) zero: P, colsums, accumulators, done flag
__global__ void zero_kernel() {
    int gid = blockIdx.x * blockDim.x + threadIdx.x;
    int stride = gridDim.x * blockDim.x;
    float4* P4 = (float4*)g_P;
    const int n4 = PTOT / 4;
    for (int i = gid; i < n4; i += stride) P4[i] = make_float4(0.f, 0.f, 0.f, 0.f);
    if (gid < HDIM * C1D) g_cs_seen[gid] = 0.0f;
    if (gid < HDIM * C2D) g_cs_unseen[gid] = 0.0f;
    if (gid < 2) g_acc[gid] = 0.0;
    if (gid == 0) g_done = 0;
}

// ---------------------------------------------------------------------------
// 2) Fused kernel: per (h,n) row, one warp computes BOTH softmaxes, extracts
//    sparse entries (val > TAU) into smem, accumulates colsums, then scatters
//    the outer product into dense P. No global sparse lists, no extra launch.
template <int C, bool SEEN>
__device__ __forceinline__ int row_softmax_extract(
        const float* __restrict__ x, int r, int lane,
        int* warp_cnt, float* lvals, unsigned short* lcols) {
    constexpr int VE = C / 128;              // float4 per lane (32 lanes)
    constexpr int K  = SEEN ? K1 : K2;
    float* __restrict__ colsum = SEEN ? g_cs_seen : g_cs_unseen;

    int h = r >> 12;
    int n = r & (NDIM - 1);
    int v = n >> 11;
    int b = n & (BDIM - 1);
    const float4* row = (const float4*)(x + ((size_t)((v * HDIM + h) * BDIM + b)) * C);

    float4 vv[VE];
    float m = -1e30f;
#pragma unroll
    for (int i = 0; i < VE; i++) {
        vv[i] = row[lane + i * 32];
        m = fmaxf(m, fmaxf(fmaxf(vv[i].x, vv[i].y), fmaxf(vv[i].z, vv[i].w)));
    }
#pragma unroll
    for (int off = 16; off > 0; off >>= 1)
        m = fmaxf(m, __shfl_xor_sync(0xFFFFFFFFu, m, off));

    float ssum = 0.0f;
#pragma unroll
    for (int i = 0; i < VE; i++) {
        vv[i].x = __expf((vv[i].x - m) * INV_TEMP);
        vv[i].y = __expf((vv[i].y - m) * INV_TEMP);
        vv[i].z = __expf((vv[i].z - m) * INV_TEMP);
        vv[i].w = __expf((vv[i].w - m) * INV_TEMP);
        ssum += vv[i].x + vv[i].y + vv[i].z + vv[i].w;
    }
#pragma unroll
    for (int off = 16; off > 0; off >>= 1)
        ssum += __shfl_xor_sync(0xFFFFFFFFu, ssum, off);
    float inv = 1.0f / ssum;

    if (lane == 0) *warp_cnt = 0;
    __syncwarp();

    float* cs = colsum + h * C;
#pragma unroll
    for (int i = 0; i < VE; i++) {
        int c = (lane + i * 32) * 4;
        float vals[4] = {vv[i].x * inv, vv[i].y * inv, vv[i].z * inv, vv[i].w * inv};
#pragma unroll
        for (int q = 0; q < 4; q++) {
            float val = vals[q];
            if (val > TAU) {
                int pos = atomicAdd(warp_cnt, 1);
                if (pos < K) {
                    lvals[pos] = val;
                    lcols[pos] = (unsigned short)(c + q);
                }
                atomicAdd(&cs[c + q], val);
            }
        }
    }
    __syncwarp();
    return min(*warp_cnt, K);
}

__global__ void __launch_bounds__(256) softmax_scatter_kernel(
        const float* __restrict__ xs, const float* __restrict__ xu) {
    __shared__ int wc[8];
    __shared__ float sv[8][K1];
    __shared__ unsigned short sc[8][K1];
    __shared__ float uv[8][K2];
    __shared__ unsigned short uc[8][K2];

    int w = threadIdx.x >> 5;
    int lane = threadIdx.x & 31;
    int r = blockIdx.x * 8 + w;        // row = h*N + n, 16384 rows
    int h = r >> 12;

    int ks = row_softmax_extract<C1D, true >(xs, r, lane, &wc[w], sv[w], sc[w]);
    int ku = row_softmax_extract<C2D, false>(xu, r, lane, &wc[w], uv[w], uc[w]);

    if (ks > 0) {
        float* Ph = g_P + (size_t)h * C2D * C1D;
        int total = ks * ku;
        for (int idx = lane; idx < total; idx += 32) {
            int iu = idx / ks;
            int is = idx - iu * ks;
            atomicAdd(&Ph[(size_t)uc[w][iu] * C1D + sc[w][is]],
                      uv[w][iu] * sv[w][is]);
        }
    }
}

// ---------------------------------------------------------------------------
// 3) stats: logps, EPS baseline into acc0, p_unseen entropy into acc1.
__global__ void stats_kernel() {
    __shared__ float redA[256];
    __shared__ float redB[256];
    int idx = blockIdx.x * blockDim.x + threadIdx.x;   // 8192 threads
    int tid = threadIdx.x;

    float e0 = 0.0f, e1 = 0.0f;
    if (idx < HDIM * C1D) {
        float p = fmaxf(g_cs_seen[idx] * (1.0f / NDIM), EPSV);
        float l = __logf(p);
        g_logps[idx] = l;
        // baseline: every one of the C2 cells in this column contributes
        // EPS*(lnEPS - l) unless corrected by the scan kernel.
        e0 = EPSV * (LN_EPS - l) * (float)C2D;
    }
    if (idx < HDIM * C2D) {
        float pu = fmaxf(g_cs_unseen[idx] * (1.0f / NDIM), EPSV);
        e1 = pu * __logf(pu);
    }
    redA[tid] = e0; redB[tid] = e1; __syncthreads();
#pragma unroll
    for (int s = 128; s > 0; s >>= 1) {
        if (tid < s) { redA[tid] += redA[tid + s]; redB[tid] += redB[tid + s]; }
        __syncthreads();
    }
    if (tid == 0) {
        atomicAdd(&g_acc[0], (double)redA[0]);
        atomicAdd(&g_acc[1], (double)redB[0]);
    }
}

// ---------------------------------------------------------------------------
// 4) scan corrections + finalize. Each thread owns 32 CONTIGUOUS floats
//    (8 independent float4 loads, fully unrolled -> MLP=8).
// corr = pc*(ln pc - lps) - EPS*(lnEPS - lps), pc = max(P/N, EPS)
__global__ void __launch_bounds__(256) scan_finalize_kernel(float* __restrict__ out) {
    __shared__ float red[256];
    int t = blockIdx.x * blockDim.x + threadIdx.x;   // 262144 threads
    int base = t * 32;                                // 32 floats each
    int h = base >> 21;                               // C2D*C1D = 2^21
    const float* lp = g_logps + h * C1D + (base & (C1D - 1));
    const float4* P4 = (const float4*)(g_P + base);
    const float invN = 1.0f / NDIM;

    float4 p[8];
#pragma unroll
    for (int i = 0; i < 8; i++) p[i] = P4[i];

    float local = 0.0f;
#pragma unroll
    for (int i = 0; i < 8; i++) {
        float pv[4] = {p[i].x, p[i].y, p[i].z, p[i].w};
#pragma unroll
        for (int q = 0; q < 4; q++) {
            if (pv[q] != 0.0f) {
                float l = lp[i * 4 + q];
                float pc = fmaxf(pv[q] * invN, EPSV);
                local += pc * (__logf(pc) - l) - EPSV * (LN_EPS - l);
            }
        }
    }

    int tid = threadIdx.x;
    red[tid] = local; __syncthreads();
#pragma unroll
    for (int s = 128; s > 0; s >>= 1) {
        if (tid < s) red[tid] += red[tid + s];
        __syncthreads();
    }
    if (tid == 0) {
        atomicAdd(&g_acc[0], (double)red[0]);
        __threadfence();
        int prev = atomicAdd(&g_done, 1);
        if (prev == (int)gridDim.x - 1) {
            out[0] = (float)((-g_acc[0] + g_acc[1]) / (double)HDIM);
        }
    }
}

// ---------------------------------------------------------------------------
extern "C" void kernel_launch(void* const* d_in, const int* in_sizes, int n_in,
                              void* d_out, int out_size) {
    const float* x_seen;
    const float* x_unseen;
    if (in_sizes[0] == VDIM * HDIM * BDIM * C1D) {
        x_seen   = (const float*)d_in[0];
        x_unseen = (const float*)d_in[1];
    } else {
        x_seen   = (const float*)d_in[1];
        x_unseen = (const float*)d_in[0];
    }
    float* out = (float*)d_out;

    zero_kernel<<<2048, 256>>>();                            // 1
    softmax_scatter_kernel<<<2048, 256>>>(x_seen, x_unseen); // 2 (fused)
    stats_kernel<<<32, 256>>>();                             // 3
    scan_finalize_kernel<<<1024, 256>>>(out);                // 4
}

// round 9
// speedup vs baseline: 1.1683x; 1.1683x over previous
#include <cuda_runtime.h>
#include <cuda_bf16.h>
#include <cstdint>
#include <math.h>

// Problem constants: x_seen (v=2, h=4, B=2048, C1=1024), x_unseen (2,4,2048,2048)
#define VDIM 2
#define HDIM 4
#define BDIM 2048
#define NDIM 4096   // v*B
#define C1D  1024
#define C2D  2048
#define EPSV 1e-07f
#define LN_EPS (-16.118095651f)
#define INV_TEMP 20.0f
#define TAU 1e-8f
#define K1 96       // max kept entries per seen row  (C1=1024)
#define K2 128      // max kept entries per unseen row (C2=2048)

#define PTOT (HDIM * C2D * C1D)   // 8388608 cells

// ---------------------------------------------------------------------------
// Device globals (never passed as kernel args from host — GB300/ATS trap!)
// Invariant maintained across graph replays: g_P == 0, colsums == 0,
// g_acc == 0, g_done == 0 at kernel_launch entry. First run: .bss zeros.
// Each replay: scan_finalize restores all of them.
__device__ float  g_P[PTOT];        // dense p_joint accum, 32MB
__device__ float  g_cs_seen[HDIM * C1D];
__device__ float  g_cs_unseen[HDIM * C2D];
__device__ float  g_logps[HDIM * C1D];
__device__ double g_acc[2];         // [0]=sum p(lnp-lps) incl. EPS baseline, [1]=sum pu ln pu
__device__ int    g_done;

// ---------------------------------------------------------------------------
// 1) Fused kernel: per (h,n) row, one warp computes BOTH softmaxes, extracts
//    sparse entries (val > TAU) into smem, accumulates colsums, then scatters
//    the outer product into dense P.
template <int C, bool SEEN>
__device__ __forceinline__ int row_softmax_extract(
        const float* __restrict__ x, int r, int lane,
        int* warp_cnt, float* lvals, unsigned short* lcols) {
    constexpr int VE = C / 128;              // float4 per lane (32 lanes)
    constexpr int K  = SEEN ? K1 : K2;
    float* __restrict__ colsum = SEEN ? g_cs_seen : g_cs_unseen;

    int h = r >> 12;
    int n = r & (NDIM - 1);
    int v = n >> 11;
    int b = n & (BDIM - 1);
    const float4* row = (const float4*)(x + ((size_t)((v * HDIM + h) * BDIM + b)) * C);

    float4 vv[VE];
    float m = -1e30f;
#pragma unroll
    for (int i = 0; i < VE; i++) {
        vv[i] = row[lane + i * 32];
        m = fmaxf(m, fmaxf(fmaxf(vv[i].x, vv[i].y), fmaxf(vv[i].z, vv[i].w)));
    }
#pragma unroll
    for (int off = 16; off > 0; off >>= 1)
        m = fmaxf(m, __shfl_xor_sync(0xFFFFFFFFu, m, off));

    float ssum = 0.0f;
#pragma unroll
    for (int i = 0; i < VE; i++) {
        vv[i].x = __expf((vv[i].x - m) * INV_TEMP);
        vv[i].y = __expf((vv[i].y - m) * INV_TEMP);
        vv[i].z = __expf((vv[i].z - m) * INV_TEMP);
        vv[i].w = __expf((vv[i].w - m) * INV_TEMP);
        ssum += vv[i].x + vv[i].y + vv[i].z + vv[i].w;
    }
#pragma unroll
    for (int off = 16; off > 0; off >>= 1)
        ssum += __shfl_xor_sync(0xFFFFFFFFu, ssum, off);
    float inv = 1.0f / ssum;

    if (lane == 0) *warp_cnt = 0;
    __syncwarp();

    float* cs = colsum + h * C;
#pragma unroll
    for (int i = 0; i < VE; i++) {
        int c = (lane + i * 32) * 4;
        float vals[4] = {vv[i].x * inv, vv[i].y * inv, vv[i].z * inv, vv[i].w * inv};
#pragma unroll
        for (int q = 0; q < 4; q++) {
            float val = vals[q];
            if (val > TAU) {
                int pos = atomicAdd(warp_cnt, 1);
                if (pos < K) {
                    lvals[pos] = val;
                    lcols[pos] = (unsigned short)(c + q);
                }
                atomicAdd(&cs[c + q], val);
            }
        }
    }
    __syncwarp();
    return min(*warp_cnt, K);
}

__global__ void __launch_bounds__(256) softmax_scatter_kernel(
        const float* __restrict__ xs, const float* __restrict__ xu) {
    __shared__ int wc[8];
    __shared__ float sv[8][K1];
    __shared__ unsigned short sc[8][K1];
    __shared__ float uv[8][K2];
    __shared__ unsigned short uc[8][K2];

    int w = threadIdx.x >> 5;
    int lane = threadIdx.x & 31;
    int r = blockIdx.x * 8 + w;        // row = h*N + n, 16384 rows
    int h = r >> 12;

    int ks = row_softmax_extract<C1D, true >(xs, r, lane, &wc[w], sv[w], sc[w]);
    int ku = row_softmax_extract<C2D, false>(xu, r, lane, &wc[w], uv[w], uc[w]);

    if (ks > 0) {
        float* Ph = g_P + (size_t)h * C2D * C1D;
        int total = ks * ku;
        for (int idx = lane; idx < total; idx += 32) {
            int iu = idx / ks;
            int is = idx - iu * ks;
            atomicAdd(&Ph[(size_t)uc[w][iu] * C1D + sc[w][is]],
                      uv[w][iu] * sv[w][is]);
        }
    }
}

// ---------------------------------------------------------------------------
// 2) stats: logps, EPS baseline into acc0, p_unseen entropy into acc1.
__global__ void stats_kernel() {
    __shared__ float redA[256];
    __shared__ float redB[256];
    int idx = blockIdx.x * blockDim.x + threadIdx.x;   // 8192 threads
    int tid = threadIdx.x;

    float e0 = 0.0f, e1 = 0.0f;
    if (idx < HDIM * C1D) {
        float p = fmaxf(g_cs_seen[idx] * (1.0f / NDIM), EPSV);
        float l = __logf(p);
        g_logps[idx] = l;
        // baseline: every one of the C2 cells in this column contributes
        // EPS*(lnEPS - l) unless corrected by the scan kernel.
        e0 = EPSV * (LN_EPS - l) * (float)C2D;
    }
    if (idx < HDIM * C2D) {
        float pu = fmaxf(g_cs_unseen[idx] * (1.0f / NDIM), EPSV);
        e1 = pu * __logf(pu);
    }
    redA[tid] = e0; redB[tid] = e1; __syncthreads();
#pragma unroll
    for (int s = 128; s > 0; s >>= 1) {
        if (tid < s) { redA[tid] += redA[tid + s]; redB[tid] += redB[tid + s]; }
        __syncthreads();
    }
    if (tid == 0) {
        atomicAdd(&g_acc[0], (double)redA[0]);
        atomicAdd(&g_acc[1], (double)redB[0]);
    }
}

// ---------------------------------------------------------------------------
// 3) scan corrections + finalize + state restore.
//    Block b owns float4 range [b*2048, (b+1)*2048): 8 coalesced unrolled
//    loads per thread (i*256 + tid). h = b>>8 (256 blocks per head);
//    c1 of float4 (i,tid) = tid*4 for every i -> one logps float4 per thread.
//    corr = pc*(ln pc - lps) - EPS*(lnEPS - lps), pc = max(P/N, EPS).
//    Restores g_P to zero (conditional write), zeroes colsums, resets acc/done.
__global__ void __launch_bounds__(256) scan_finalize_kernel(float* __restrict__ out) {
    __shared__ float red[256];
    int tid = threadIdx.x;
    int b = blockIdx.x;                      // 1024 blocks
    int h = b >> 8;
    float4* P4 = (float4*)g_P + (size_t)b * 2048;
    const float4 lp4 = *((const float4*)(g_logps + h * C1D) + tid);
    const float lp[4] = {lp4.x, lp4.y, lp4.z, lp4.w};
    const float invN = 1.0f / NDIM;
    const float4 z4 = make_float4(0.f, 0.f, 0.f, 0.f);

    // zero colsums for the next replay (stats consumed them last launch)
    {
        int zi = b * 256 + tid;
        if (zi < HDIM * C1D) g_cs_seen[zi] = 0.0f;
        if (zi < HDIM * C2D) g_cs_unseen[zi] = 0.0f;
    }

    float4 p[8];
#pragma unroll
    for (int i = 0; i < 8; i++) p[i] = P4[i * 256 + tid];

    float local = 0.0f;
#pragma unroll
    for (int i = 0; i < 8; i++) {
        float pv[4] = {p[i].x, p[i].y, p[i].z, p[i].w};
        bool any = (pv[0] != 0.0f) | (pv[1] != 0.0f) | (pv[2] != 0.0f) | (pv[3] != 0.0f);
        if (any) {
#pragma unroll
            for (int q = 0; q < 4; q++) {
                if (pv[q] != 0.0f) {
                    float l = lp[q];
                    float pc = fmaxf(pv[q] * invN, EPSV);
                    local += pc * (__logf(pc) - l) - EPSV * (LN_EPS - l);
                }
            }
            P4[i * 256 + tid] = z4;          // restore to zero for next replay
        }
    }

    red[tid] = local; __syncthreads();
#pragma unroll
    for (int s = 128; s > 0; s >>= 1) {
        if (tid < s) red[tid] += red[tid + s];
        __syncthreads();
    }
    if (tid == 0) {
        atomicAdd(&g_acc[0], (double)red[0]);
        __threadfence();
        int prev = atomicAdd(&g_done, 1);
        if (prev == (int)gridDim.x - 1) {
            out[0] = (float)((-g_acc[0] + g_acc[1]) / (double)HDIM);
            // reset accumulators for next replay
            g_acc[0] = 0.0;
            g_acc[1] = 0.0;
            g_done = 0;
        }
    }
}

// ---------------------------------------------------------------------------
extern "C" void kernel_launch(void* const* d_in, const int* in_sizes, int n_in,
                              void* d_out, int out_size) {
    const float* x_seen;
    const float* x_unseen;
    if (in_sizes[0] == VDIM * HDIM * BDIM * C1D) {
        x_seen   = (const float*)d_in[0];
        x_unseen = (const float*)d_in[1];
    } else {
        x_seen   = (const float*)d_in[1];
        x_unseen = (const float*)d_in[0];
    }
    float* out = (float*)d_out;

    softmax_scatter_kernel<<<2048, 256>>>(x_seen, x_unseen); // 1 (fused)
    stats_kernel<<<32, 256>>>();                             // 2
    scan_finalize_kernel<<<1024, 256>>>(out);                // 3
}

// round 10
// speedup vs baseline: 1.3251x; 1.1342x over previous
#include <cuda_runtime.h>
#include <cuda_bf16.h>
#include <cstdint>
#include <math.h>

// Problem constants: x_seen (v=2, h=4, B=2048, C1=1024), x_unseen (2,4,2048,2048)
#define VDIM 2
#define HDIM 4
#define BDIM 2048
#define NDIM 4096   // v*B
#define C1D  1024
#define C2D  2048
#define EPSV 1e-07f
#define LN_EPS (-16.118095651f)
#define INV_TEMP 20.0f
#define TAU 1e-8f
#define K1 96       // max kept entries per seen row  (C1=1024)
#define K2 128      // max kept entries per unseen row (C2=2048)

#define PTOT (HDIM * C2D * C1D)   // 8388608 cells

// ---------------------------------------------------------------------------
// Device globals (never passed as kernel args from host — GB300/ATS trap!)
// Invariant maintained across graph replays: g_P == 0, colsums == 0,
// g_acc == 0, g_done == 0 at kernel_launch entry. First run: .bss zeros.
// Each replay: scan_finalize restores all of them.
__device__ float  g_P[PTOT];        // dense p_joint accum, 32MB
__device__ float  g_cs_seen[HDIM * C1D];
__device__ float  g_cs_unseen[HDIM * C2D];
__device__ float  g_logps[HDIM * C1D];
__device__ double g_acc[2];         // [0]=sum p(lnp-lps) incl. EPS baseline, [1]=sum pu ln pu
__device__ int    g_done;

// ---------------------------------------------------------------------------
// 1) Fused kernel: per (h,n) row, one warp does a TWO-PASS softmax (pass 1:
//    running max only; pass 2: reload from L1/L2, exp, sum, extract e>TAU),
//    then normalizes the ~12 extracted entries in smem, does colsum atomics
//    on just those entries, and scatters the outer product into dense P.
//    No large register arrays -> high occupancy -> HBM-bound as intended.
template <int C, bool SEEN>
__device__ __forceinline__ int row_softmax_extract(
        const float* __restrict__ x, int r, int lane,
        int* warp_cnt, float* lvals, unsigned short* lcols) {
    constexpr int VE = C / 128;              // float4 per lane (32 lanes)
    constexpr int K  = SEEN ? K1 : K2;
    float* __restrict__ colsum = SEEN ? g_cs_seen : g_cs_unseen;

    int h = r >> 12;
    int n = r & (NDIM - 1);
    int v = n >> 11;
    int b = n & (BDIM - 1);
    const float4* row = (const float4*)(x + ((size_t)((v * HDIM + h) * BDIM + b)) * C);

    // Pass 1: running max, values discarded (no register arrays)
    float m = -1e30f;
#pragma unroll
    for (int i = 0; i < VE; i++) {
        float4 vv = row[lane + i * 32];
        m = fmaxf(m, fmaxf(fmaxf(vv.x, vv.y), fmaxf(vv.z, vv.w)));
    }
#pragma unroll
    for (int off = 16; off > 0; off >>= 1)
        m = fmaxf(m, __shfl_xor_sync(0xFFFFFFFFu, m, off));

    if (lane == 0) *warp_cnt = 0;
    __syncwarp();

    // Pass 2: reload (L1/L2 hit), exp, sum, extract e > TAU (superset of
    // val > TAU since ssum >= 1; near-threshold entries are negligible).
    float ssum = 0.0f;
#pragma unroll
    for (int i = 0; i < VE; i++) {
        float4 vv = row[lane + i * 32];
        float e0 = __expf((vv.x - m) * INV_TEMP);
        float e1 = __expf((vv.y - m) * INV_TEMP);
        float e2 = __expf((vv.z - m) * INV_TEMP);
        float e3 = __expf((vv.w - m) * INV_TEMP);
        ssum += e0 + e1 + e2 + e3;
        int c = (lane + i * 32) * 4;
        if (e0 > TAU) { int p = atomicAdd(warp_cnt, 1); if (p < K) { lvals[p] = e0; lcols[p] = (unsigned short)(c + 0); } }
        if (e1 > TAU) { int p = atomicAdd(warp_cnt, 1); if (p < K) { lvals[p] = e1; lcols[p] = (unsigned short)(c + 1); } }
        if (e2 > TAU) { int p = atomicAdd(warp_cnt, 1); if (p < K) { lvals[p] = e2; lcols[p] = (unsigned short)(c + 2); } }
        if (e3 > TAU) { int p = atomicAdd(warp_cnt, 1); if (p < K) { lvals[p] = e3; lcols[p] = (unsigned short)(c + 3); } }
    }
#pragma unroll
    for (int off = 16; off > 0; off >>= 1)
        ssum += __shfl_xor_sync(0xFFFFFFFFu, ssum, off);
    float inv = 1.0f / ssum;

    __syncwarp();
    int cnt = min(*warp_cnt, K);

    // normalize stored entries + colsum atomics (only ~cnt entries)
    float* cs = colsum + h * C;
    for (int i = lane; i < cnt; i += 32) {
        float val = lvals[i] * inv;
        lvals[i] = val;
        atomicAdd(&cs[lcols[i]], val);
    }
    __syncwarp();
    return cnt;
}

__global__ void __launch_bounds__(256) softmax_scatter_kernel(
        const float* __restrict__ xs, const float* __restrict__ xu) {
    __shared__ int wc[8];
    __shared__ float sv[8][K1];
    __shared__ unsigned short sc[8][K1];
    __shared__ float uv[8][K2];
    __shared__ unsigned short uc[8][K2];

    int w = threadIdx.x >> 5;
    int lane = threadIdx.x & 31;
    int r = blockIdx.x * 8 + w;        // row = h*N + n, 16384 rows
    int h = r >> 12;

    int ks = row_softmax_extract<C1D, true >(xs, r, lane, &wc[w], sv[w], sc[w]);
    int ku = row_softmax_extract<C2D, false>(xu, r, lane, &wc[w], uv[w], uc[w]);

    if (ks > 0) {
        float* Ph = g_P + (size_t)h * C2D * C1D;
        int total = ks * ku;
        for (int idx = lane; idx < total; idx += 32) {
            int iu = idx / ks;
            int is = idx - iu * ks;
            atomicAdd(&Ph[(size_t)uc[w][iu] * C1D + sc[w][is]],
                      uv[w][iu] * sv[w][is]);
        }
    }
}

// ---------------------------------------------------------------------------
// 2) stats: logps, EPS baseline into acc0, p_unseen entropy into acc1.
__global__ void stats_kernel() {
    __shared__ float redA[256];
    __shared__ float redB[256];
    int idx = blockIdx.x * blockDim.x + threadIdx.x;   // 8192 threads
    int tid = threadIdx.x;

    float e0 = 0.0f, e1 = 0.0f;
    if (idx < HDIM * C1D) {
        float p = fmaxf(g_cs_seen[idx] * (1.0f / NDIM), EPSV);
        float l = __logf(p);
        g_logps[idx] = l;
        // baseline: every one of the C2 cells in this column contributes
        // EPS*(lnEPS - l) unless corrected by the scan kernel.
        e0 = EPSV * (LN_EPS - l) * (float)C2D;
    }
    if (idx < HDIM * C2D) {
        float pu = fmaxf(g_cs_unseen[idx] * (1.0f / NDIM), EPSV);
        e1 = pu * __logf(pu);
    }
    redA[tid] = e0; redB[tid] = e1; __syncthreads();
#pragma unroll
    for (int s = 128; s > 0; s >>= 1) {
        if (tid < s) { redA[tid] += redA[tid + s]; redB[tid] += redB[tid + s]; }
        __syncthreads();
    }
    if (tid == 0) {
        atomicAdd(&g_acc[0], (double)redA[0]);
        atomicAdd(&g_acc[1], (double)redB[0]);
    }
}

// ---------------------------------------------------------------------------
// 3) scan corrections + finalize + state restore.
//    Block b owns float4 range [b*2048, (b+1)*2048): 8 coalesced unrolled
//    loads per thread (i*256 + tid). h = b>>8 (256 blocks per head);
//    c1 of float4 (i,tid) = tid*4 for every i -> one logps float4 per thread.
//    corr = pc*(ln pc - lps) - EPS*(lnEPS - lps), pc = max(P/N, EPS).
//    Restores g_P to zero (conditional write), zeroes colsums, resets acc/done.
__global__ void __launch_bounds__(256) scan_finalize_kernel(float* __restrict__ out) {
    __shared__ float red[256];
    int tid = threadIdx.x;
    int b = blockIdx.x;                      // 1024 blocks
    int h = b >> 8;
    float4* P4 = (float4*)g_P + (size_t)b * 2048;
    const float4 lp4 = *((const float4*)(g_logps + h * C1D) + tid);
    const float lp[4] = {lp4.x, lp4.y, lp4.z, lp4.w};
    const float invN = 1.0f / NDIM;
    const float4 z4 = make_float4(0.f, 0.f, 0.f, 0.f);

    // zero colsums for the next replay (stats consumed them last launch)
    {
        int zi = b * 256 + tid;
        if (zi < HDIM * C1D) g_cs_seen[zi] = 0.0f;
        if (zi < HDIM * C2D) g_cs_unseen[zi] = 0.0f;
    }

    float4 p[8];
#pragma unroll
    for (int i = 0; i < 8; i++) p[i] = P4[i * 256 + tid];

    float local = 0.0f;
#pragma unroll
    for (int i = 0; i < 8; i++) {
        float pv[4] = {p[i].x, p[i].y, p[i].z, p[i].w};
        bool any = (pv[0] != 0.0f) | (pv[1] != 0.0f) | (pv[2] != 0.0f) | (pv[3] != 0.0f);
        if (any) {
#pragma unroll
            for (int q = 0; q < 4; q++) {
                if (pv[q] != 0.0f) {
                    float l = lp[q];
                    float pc = fmaxf(pv[q] * invN, EPSV);
                    local += pc * (__logf(pc) - l) - EPSV * (LN_EPS - l);
                }
            }
            P4[i * 256 + tid] = z4;          // restore to zero for next replay
        }
    }

    red[tid] = local; __syncthreads();
#pragma unroll
    for (int s = 128; s > 0; s >>= 1) {
        if (tid < s) red[tid] += red[tid + s];
        __syncthreads();
    }
    if (tid == 0) {
        atomicAdd(&g_acc[0], (double)red[0]);
        __threadfence();
        int prev = atomicAdd(&g_done, 1);
        if (prev == (int)gridDim.x - 1) {
            out[0] = (float)((-g_acc[0] + g_acc[1]) / (double)HDIM);
            // reset accumulators for next replay
            g_acc[0] = 0.0;
            g_acc[1] = 0.0;
            g_done = 0;
        }
    }
}

// ---------------------------------------------------------------------------
extern "C" void kernel_launch(void* const* d_in, const int* in_sizes, int n_in,
                              void* d_out, int out_size) {
    const float* x_seen;
    const float* x_unseen;
    if (in_sizes[0] == VDIM * HDIM * BDIM * C1D) {
        x_seen   = (const float*)d_in[0];
        x_unseen = (const float*)d_in[1];
    } else {
        x_seen   = (const float*)d_in[1];
        x_unseen = (const float*)d_in[0];
    }
    float* out = (float*)d_out;

    softmax_scatter_kernel<<<2048, 256>>>(x_seen, x_unseen); // 1 (fused)
    stats_kernel<<<32, 256>>>();                             // 2
    scan_finalize_kernel<<<1024, 256>>>(out);                // 3
}